// round 9
// baseline (speedup 1.0000x reference)
#include <cuda_runtime.h>
#include <cstdint>

#define N_PTS 16384
#define M_PTS 4096
#define KNN_K 16
#define EMB   64
#define NEDGE (N_PTS*KNN_K)   // 262144
#define FLT_MAX_C 3.402823466e+38f

#define GRID_C 8              // 8x8x8 = 512 cells
#define NCELL  (GRID_C*GRID_C*GRID_C)

// ---------------- device scratch (static globals: allocation-free) ----------
__device__ int      g_idx[M_PTS];
__device__ float4   g_ps[M_PTS];          // sampled pos: x,y,z, sumsq
__device__ float    g_xs[M_PTS*EMB];      // gathered features
__device__ float    g_delta[M_PTS*3];     // h-MLP output per sampled point
__device__ float    g_u[N_PTS*EMB];       // x @ f_w1[3:,:] + f_b1  (pre-ReLU)
__device__ float    g_sn[N_PTS];          // ||pos||^2 per point
__device__ int      g_nbr[NEDGE];         // knn neighbor ids
__device__ float    g_hidden[NEDGE*EMB];  // per-edge layer-1 post-ReLU
__device__ unsigned g_aggr[M_PTS*EMB];    // encoded float max accumulators

// spatial-sort scratch for FPS
__device__ int            g_cnt[NCELL];
__device__ int            g_cur[NCELL];
__device__ int            g_cell[N_PTS];
__device__ float          g_rx[N_PTS], g_ry[N_PTS], g_rz[N_PTS];  // sorted coords
__device__ unsigned short g_rid16[N_PTS]; // sorted order -> original index

// order-preserving float<->uint encoding for atomicMax
__device__ __forceinline__ unsigned encf(float f) {
    unsigned u = __float_as_uint(f);
    return (u & 0x80000000u) ? ~u : (u | 0x80000000u);
}
__device__ __forceinline__ float decf(unsigned u) {
    return (u & 0x80000000u) ? __uint_as_float(u & 0x7FFFFFFFu) : __uint_as_float(~u);
}

// u64 max via shuffle butterfly (all lanes end with the max)
__device__ __forceinline__ unsigned long long shflmax64(unsigned long long k) {
#pragma unroll
    for (int o = 16; o; o >>= 1) {
        unsigned long long k2 = __shfl_xor_sync(0xFFFFFFFFu, k, o);
        k = (k2 > k) ? k2 : k;
    }
    return k;
}

// ---------------- ||pos||^2 + zero cell counters ----------------------------
__global__ void sn_kernel(const float* __restrict__ pos) {
    int i = blockIdx.x * 256 + threadIdx.x;
    if (i < NCELL) g_cnt[i] = 0;
    if (i < N_PTS) {
        float x = pos[3*i], y = pos[3*i+1], z = pos[3*i+2];
        g_sn[i] = __fadd_rn(__fadd_rn(__fmul_rn(x,x), __fmul_rn(y,y)), __fmul_rn(z,z));
    }
}

// ---------------- Morton cell id + histogram --------------------------------
// Bit-interleaved cell order: an equal-count contiguous run of sorted points
// is a compact cube-ish region -> tight warp bboxes -> effective pruning.
__global__ void cell_kernel(const float* __restrict__ pos) {
    int i = blockIdx.x * 256 + threadIdx.x;
    if (i < N_PTS) {
        float x = pos[3*i], y = pos[3*i+1], z = pos[3*i+2];
        int cx = min(GRID_C-1, max(0, (int)((x + 5.0f) * 0.8f)));
        int cy = min(GRID_C-1, max(0, (int)((y + 5.0f) * 0.8f)));
        int cz = min(GRID_C-1, max(0, (int)((z + 5.0f) * 0.8f)));
        int c = 0;
#pragma unroll
        for (int b = 0; b < 3; b++) {
            c |= ((cx >> b) & 1) << (3*b + 2);
            c |= ((cy >> b) & 1) << (3*b + 1);
            c |= ((cz >> b) & 1) << (3*b + 0);
        }
        g_cell[i] = c;
        atomicAdd(&g_cnt[c], 1);
    }
}

// ---------------- exclusive scan of 512 cell counts -> g_cur ----------------
__global__ void scan_kernel() {
    __shared__ int ws[16];
    int t = threadIdx.x;           // 512 threads, 1 cell each
    int lane = t & 31, wid = t >> 5;
    int s = g_cnt[t];
    int inc = s;
#pragma unroll
    for (int o = 1; o < 32; o <<= 1) {
        int v = __shfl_up_sync(0xFFFFFFFFu, inc, o);
        if (lane >= o) inc += v;
    }
    if (lane == 31) ws[wid] = inc;
    __syncthreads();
    if (t < 16) {
        int v = ws[t], iv = v;
#pragma unroll
        for (int o = 1; o < 16; o <<= 1) {
            int u = __shfl_up_sync(0xFFFFu, iv, o);
            if (t >= o) iv += u;
        }
        ws[t] = iv - v;            // exclusive warp base
    }
    __syncthreads();
    g_cur[t] = ws[wid] + inc - s;  // exclusive prefix
}

// ---------------- scatter coords+ids into Morton-sorted order ---------------
__global__ void scatter_kernel(const float* __restrict__ pos) {
    int i = blockIdx.x * 256 + threadIdx.x;
    if (i < N_PTS) {
        int c = g_cell[i];
        int d = atomicAdd(&g_cur[c], 1);
        g_rx[d] = pos[3*i]; g_ry[d] = pos[3*i+1]; g_rz[d] = pos[3*i+2];
        g_rid16[d] = (unsigned short)i;
    }
}

// ---------------- FPS: single CTA, conflict-free Morton-pruned updates ------
// Sorted point s lives at phys(s) = (s>>4) + (s&15)*1024, so thread t's 16
// points are at px[t + j*1024] -> lane addresses consecutive -> LDS is
// bank-conflict-FREE. Payload ((16383-orig)<<14 | s) precomputed in
// registers: hot loop has zero global loads, zero scattered LDS.
// Winner key = (md_bits<<32)|payload: max d, tie -> min original index ==
// jnp.argmax rule, order-invariant w.r.t. the nondeterministic scatter.
// Prune: warp skips iff all lanes prove every owned point has d >= md
// (margins >> fp32 rounding) -> fminf no-op, md unchanged while inactive,
// so the cached key stays exact. Zero bit drift.
__global__ __launch_bounds__(1024, 1)
void fps_kernel(const float* __restrict__ pos) {
    extern __shared__ float sm[];
    float* px = sm;
    float* py = sm + N_PTS;
    float* pz = sm + 2*N_PTS;
    __shared__ unsigned long long wk[32];
    __shared__ unsigned long long s_win;

    int t = threadIdx.x, lane = t & 31, wid = t >> 5;
    for (int i = t; i < N_PTS; i += 1024) {
        int ph = (i >> 4) + ((i & 15) << 10);
        px[ph] = g_rx[i]; py[ph] = g_ry[i]; pz[ph] = g_rz[i];
    }
    __syncthreads();

    float md[16];
    unsigned pay[16];
    float lox = FLT_MAX_C, hix = -FLT_MAX_C;
    float loy = FLT_MAX_C, hiy = -FLT_MAX_C;
    float loz = FLT_MAX_C, hiz = -FLT_MAX_C;
#pragma unroll
    for (int j = 0; j < 16; j++) {
        float x = px[t + (j << 10)], y = py[t + (j << 10)], z = pz[t + (j << 10)];
        lox = fminf(lox, x); hix = fmaxf(hix, x);
        loy = fminf(loy, y); hiy = fmaxf(hiy, y);
        loz = fminf(loz, z); hiz = fmaxf(hiz, z);
        md[j] = FLT_MAX_C;
        int s = t*16 + j;
        pay[j] = ((unsigned)(16383 - (int)g_rid16[s]) << 14) | (unsigned)s;
    }
    if (t == 0) g_idx[0] = 0;
    float lx = pos[0], ly = pos[1], lz = pos[2];   // original point 0

    unsigned long long ck = 0x7F7FFFFF00000000ull; // tmax=FLT_MAX -> first iter active

    for (int it = 1; it < M_PTS; ++it) {
        float tmax = __uint_as_float((unsigned)(ck >> 32));
        float lbx = fmaxf(fmaxf(lox - lx, lx - hix), 0.0f);
        float lby = fmaxf(fmaxf(loy - ly, ly - hiy), 0.0f);
        float lbz = fmaxf(fmaxf(loz - lz, lz - hiz), 0.0f);
        float lb2 = lbx*lbx + lby*lby + lbz*lbz;
        bool act = !(lb2 * 0.999f >= tmax * 1.0001f + 1e-8f);
        if (__ballot_sync(0xFFFFFFFFu, act)) {
            unsigned long long nk = 0;
#pragma unroll
            for (int j = 0; j < 16; j++) {
                float dx = __fsub_rn(px[t + (j << 10)], lx);
                float dy = __fsub_rn(py[t + (j << 10)], ly);
                float dz = __fsub_rn(pz[t + (j << 10)], lz);
                float d  = __fadd_rn(__fadd_rn(__fmul_rn(dx,dx), __fmul_rn(dy,dy)),
                                     __fmul_rn(dz,dz));
                float m  = fminf(md[j], d);
                md[j] = m;
                unsigned long long kj = ((unsigned long long)__float_as_uint(m) << 32)
                                      | pay[j];
                nk = (kj > nk) ? kj : nk;
            }
            ck = nk;
        }
        // stage 1: warp max
        unsigned long long k = shflmax64(ck);
        if (lane == 0) wk[wid] = k;
        __syncthreads();
        // stage 2: warp 0 reduces the 32 warp keys
        if (t < 32) {
            k = shflmax64(wk[t]);
            if (t == 0) s_win = k;
        }
        __syncthreads();
        unsigned long long w = s_win;
        int sp = (int)(w & 0x3FFF);                 // winner's sorted position
        int ph = (sp >> 4) + ((sp & 15) << 10);
        lx = px[ph]; ly = py[ph]; lz = pz[ph];
        if (t == 0) g_idx[it] = 16383 - (int)((w >> 14) & 0x3FFF);
    }
}

// ---------------- gather: x_s, pos_s (+sumsq), write pos_s to output --------
__global__ void gather_kernel(const float* __restrict__ pos, const float* __restrict__ x,
                              float* __restrict__ out) {
    int gid = blockIdx.x * 256 + threadIdx.x;   // 0 .. M*64-1
    int m = gid >> 6, c = gid & 63;
    int i = g_idx[m];
    g_xs[gid] = x[i*64 + c];
    if (c == 0) {
        float a = pos[3*i], b = pos[3*i+1], d = pos[3*i+2];
        float s = __fadd_rn(__fadd_rn(__fmul_rn(a,a), __fmul_rn(b,b)), __fmul_rn(d,d));
        g_ps[m] = make_float4(a, b, d, s);
        out[262144 + m*3 + 0] = a;
        out[262144 + m*3 + 1] = b;
        out[262144 + m*3 + 2] = d;
    }
}

// ---------------- h-MLP on sampled points: delta = h(x_s)  [M,3] ------------
__global__ void h_kernel(const float* __restrict__ w1, const float* __restrict__ b1,
                         const float* __restrict__ w2, const float* __restrict__ b2) {
    __shared__ float xr[64];
    __shared__ float hid[64];
    int m = blockIdx.x, c = threadIdx.x;
    xr[c] = g_xs[m*64 + c];
    __syncthreads();
    float h = b1[c];
#pragma unroll 8
    for (int k = 0; k < 64; k++) h = fmaf(xr[k], w1[k*64 + c], h);
    hid[c] = fmaxf(h, 0.0f);
    __syncthreads();
    if (c < 3) {
        float o = b2[c];
#pragma unroll 8
        for (int k = 0; k < 64; k++) o = fmaf(hid[k], w2[k*3 + c], o);
        g_delta[m*3 + c] = o;
    }
}

// ---------------- u = x @ f_w1[3:,:] + f_b1   [N,64] (pre-ReLU) -------------
__global__ void u_kernel(const float* __restrict__ x, const float* __restrict__ fw1,
                         const float* __restrict__ fb1) {
    __shared__ float xr[64];
    int n = blockIdx.x, c = threadIdx.x;
    xr[c] = x[n*64 + c];
    __syncthreads();
    float h = fb1[c];
#pragma unroll 8
    for (int k = 0; k < 64; k++) h = fmaf(xr[k], fw1[(3 + k)*64 + c], h);
    g_u[n*64 + c] = h;
}

// ---------------- KNN: per query scan 4096, stable top-16 -------------------
__global__ void knn_kernel(const float* __restrict__ pos, float* __restrict__ out) {
    extern __shared__ float4 sp[];
    int tid = threadIdx.x;
    for (int i = tid; i < M_PTS; i += 128) sp[i] = g_ps[i];
    __syncthreads();
    int n = blockIdx.x * 128 + tid;
    float qx = pos[3*n], qy = pos[3*n+1], qz = pos[3*n+2];
    float s_n = g_sn[n];
    float bd[KNN_K]; int bi[KNN_K];
#pragma unroll
    for (int j = 0; j < KNN_K; j++) { bd[j] = FLT_MAX_C; bi[j] = 0x7FFFFFFF; }
    float worst = FLT_MAX_C;
    for (int m = 0; m < M_PTS; m++) {
        float4 q = sp[m];
        float dot = __fmaf_rn(qz, q.z, __fmaf_rn(qy, q.y, __fmul_rn(qx, q.x)));
        float d2 = __fsub_rn(__fadd_rn(s_n, q.w), __fmul_rn(2.0f, dot));
        if (d2 < worst) {                   // strict: equal d2 -> earlier index kept
            float v = d2; int id = m;
#pragma unroll
            for (int j = 0; j < KNN_K; j++) {
                if (v < bd[j]) {
                    float tv = bd[j]; bd[j] = v;  v = tv;
                    int   ti = bi[j]; bi[j] = id; id = ti;
                }
            }
            worst = bd[KNN_K-1];
        }
    }
    float* osrc = out + 274432;
    float* otgt = out + 536576;
#pragma unroll
    for (int j = 0; j < KNN_K; j++) {
        g_nbr[n*KNN_K + j] = bi[j];
        osrc[n*KNN_K + j] = (float)n;
        otgt[n*KNN_K + j] = (float)bi[j];
    }
}

// ---------------- zero the aggregation buffer -------------------------------
__global__ void zero_aggr_kernel() {
    g_aggr[blockIdx.x * 256 + threadIdx.x] = 0u;
}

// ---------------- per-edge layer-1: hidden = relu(u[src] + a @ W3) ----------
__global__ void hidden_kernel(const float* __restrict__ pos, const float* __restrict__ fw1) {
    __shared__ float w3[192];
    __shared__ float av[4][3];
    int tid = threadIdx.x;                 // 256
    if (tid < 192) w3[tid] = fw1[tid];     // rows 0..2 of f_w1
    int gid = blockIdx.x * 256 + tid;
    int e = gid >> 6, c = gid & 63;
    int eg = tid >> 6;
    int n = e >> 4;
    int m = g_nbr[e];
    if (c < 3) {
        float pcomp = pos[3*n + c];
        float qcomp = ((const float*)&g_ps[m])[c];
        av[eg][c] = __fadd_rn(__fsub_rn(pcomp, qcomp), g_delta[m*3 + c]);
    }
    __syncthreads();
    float h = g_u[n*64 + c];
    h = fmaf(av[eg][0], w3[c],       h);
    h = fmaf(av[eg][1], w3[64 + c],  h);
    h = fmaf(av[eg][2], w3[128 + c], h);
    g_hidden[gid] = fmaxf(h, 0.0f);
}

// ---------------- per-edge layer-2 GEMM + atomicMax aggregation -------------
__global__ __launch_bounds__(128)
void msg_kernel(const float* __restrict__ fw2, const float* __restrict__ fb2) {
    __shared__ float w2s[64*64];
    __shared__ float ht[32*65];           // padded to kill bank conflicts
    __shared__ int   tg[32];
    int tid = threadIdx.x;
    for (int i = tid; i < 4096; i += 128) w2s[i] = fw2[i];
    int e0 = blockIdx.x * 32;
    for (int i = tid; i < 2048; i += 128) {
        ht[(i >> 6)*65 + (i & 63)] = g_hidden[e0*64 + i];
    }
    if (tid < 32) tg[tid] = g_nbr[e0 + tid];
    __syncthreads();

    int te = (tid >> 4) * 4;              // edge base within tile
    int td = (tid & 15) * 4;              // output-dim base
    float acc[4][4];
    float b0 = fb2[td], b1 = fb2[td+1], b2v = fb2[td+2], b3 = fb2[td+3];
#pragma unroll
    for (int i = 0; i < 4; i++) { acc[i][0]=b0; acc[i][1]=b1; acc[i][2]=b2v; acc[i][3]=b3; }

#pragma unroll 4
    for (int k = 0; k < 64; k++) {
        float4 w = *(const float4*)&w2s[k*64 + td];
#pragma unroll
        for (int i = 0; i < 4; i++) {
            float hv = ht[(te + i)*65 + k];
            acc[i][0] = fmaf(hv, w.x, acc[i][0]);
            acc[i][1] = fmaf(hv, w.y, acc[i][1]);
            acc[i][2] = fmaf(hv, w.z, acc[i][2]);
            acc[i][3] = fmaf(hv, w.w, acc[i][3]);
        }
    }
#pragma unroll
    for (int i = 0; i < 4; i++) {
        unsigned* base = &g_aggr[tg[te + i]*64 + td];
        atomicMax(base + 0, encf(acc[i][0]));
        atomicMax(base + 1, encf(acc[i][1]));
        atomicMax(base + 2, encf(acc[i][2]));
        atomicMax(base + 3, encf(acc[i][3]));
    }
}

// ---------------- g-MLP + residual -> x_new (written as f32) ----------------
__global__ void out_kernel(const float* __restrict__ w1, const float* __restrict__ b1,
                           const float* __restrict__ w2, const float* __restrict__ b2,
                           float* __restrict__ out) {
    __shared__ float in[128];
    __shared__ float hid[64];
    int m = blockIdx.x, c = threadIdx.x;
    float xs = g_xs[m*64 + c];
    in[c] = xs;
    unsigned u = g_aggr[m*64 + c];
    in[64 + c] = (u == 0u) ? 0.0f : decf(u);   // isfinite-else-0 rule
    __syncthreads();
    float h = b1[c];
#pragma unroll 8
    for (int k = 0; k < 128; k++) h = fmaf(in[k], w1[k*64 + c], h);
    hid[c] = fmaxf(h, 0.0f);
    __syncthreads();
    float o = b2[c];
#pragma unroll 8
    for (int k = 0; k < 64; k++) o = fmaf(hid[k], w2[k*64 + c], o);
    out[m*64 + c] = xs + o;
}

// ---------------- launcher --------------------------------------------------
extern "C" void kernel_launch(void* const* d_in, const int* in_sizes, int n_in,
                              void* d_out, int out_size) {
    const float* x    = (const float*)d_in[0];
    const float* pos  = (const float*)d_in[1];
    // d_in[2] = edge_index (int64) -- unused by the reference math
    const float* h_w1 = (const float*)d_in[3];
    const float* h_b1 = (const float*)d_in[4];
    const float* h_w2 = (const float*)d_in[5];
    const float* h_b2 = (const float*)d_in[6];
    const float* f_w1 = (const float*)d_in[7];
    const float* f_b1 = (const float*)d_in[8];
    const float* f_w2 = (const float*)d_in[9];
    const float* f_b2 = (const float*)d_in[10];
    const float* g_w1 = (const float*)d_in[11];
    const float* g_b1 = (const float*)d_in[12];
    const float* g_w2 = (const float*)d_in[13];
    const float* g_b2 = (const float*)d_in[14];
    float* out = (float*)d_out;

    size_t fps_smem = (size_t)(3*N_PTS)*sizeof(float);          // 192 KB
    cudaFuncSetAttribute(fps_kernel, cudaFuncAttributeMaxDynamicSharedMemorySize, (int)fps_smem);
    cudaFuncSetAttribute(knn_kernel, cudaFuncAttributeMaxDynamicSharedMemorySize, M_PTS*16);

    sn_kernel<<<(N_PTS + 255)/256, 256>>>(pos);         // + zero g_cnt
    cell_kernel<<<(N_PTS + 255)/256, 256>>>(pos);
    scan_kernel<<<1, NCELL>>>();
    scatter_kernel<<<(N_PTS + 255)/256, 256>>>(pos);
    fps_kernel<<<1, 1024, fps_smem>>>(pos);
    gather_kernel<<<(M_PTS*EMB)/256, 256>>>(pos, x, out);
    h_kernel<<<M_PTS, 64>>>(h_w1, h_b1, h_w2, h_b2);
    u_kernel<<<N_PTS, 64>>>(x, f_w1, f_b1);
    zero_aggr_kernel<<<(M_PTS*EMB)/256, 256>>>();
    knn_kernel<<<N_PTS/128, 128, M_PTS*16>>>(pos, out);
    hidden_kernel<<<(NEDGE*EMB)/256, 256>>>(pos, f_w1);
    msg_kernel<<<NEDGE/32, 128>>>(f_w2, f_b2);
    out_kernel<<<M_PTS, 64>>>(g_w1, g_b1, g_w2, g_b2, out);
}

// round 10
// speedup vs baseline: 1.1540x; 1.1540x over previous
#include <cuda_runtime.h>
#include <cstdint>

#define N_PTS 16384
#define M_PTS 4096
#define KNN_K 16
#define EMB   64
#define NEDGE (N_PTS*KNN_K)   // 262144
#define FLT_MAX_C 3.402823466e+38f

#define GRID_C 8              // 8x8x8 = 512 cells
#define NCELL  (GRID_C*GRID_C*GRID_C)

// ---------------- device scratch (static globals: allocation-free) ----------
__device__ int      g_idx[M_PTS];
__device__ float4   g_ps[M_PTS];          // sampled pos: x,y,z, sumsq
__device__ float    g_xs[M_PTS*EMB];      // gathered features
__device__ float    g_delta[M_PTS*3];     // h-MLP output per sampled point
__device__ float    g_u[N_PTS*EMB];       // x @ f_w1[3:,:] + f_b1  (pre-ReLU)
__device__ float    g_sn[N_PTS];          // ||pos||^2 per point
__device__ int      g_nbr[NEDGE];         // knn neighbor ids
__device__ float    g_hidden[NEDGE*EMB];  // per-edge layer-1 post-ReLU
__device__ unsigned g_aggr[M_PTS*EMB];    // encoded float max accumulators

// spatial-sort scratch for FPS  (g_cnt zero-initialized at load; scan_kernel
// re-zeroes it after use so every graph replay sees a clean histogram)
__device__ int            g_cnt[NCELL];
__device__ int            g_cur[NCELL];
__device__ int            g_cell[N_PTS];
__device__ float          g_rx[N_PTS], g_ry[N_PTS], g_rz[N_PTS];  // sorted coords
__device__ unsigned short g_rid16[N_PTS]; // sorted order -> original index

// order-preserving float<->uint encoding for atomicMax
__device__ __forceinline__ unsigned encf(float f) {
    unsigned u = __float_as_uint(f);
    return (u & 0x80000000u) ? ~u : (u | 0x80000000u);
}
__device__ __forceinline__ float decf(unsigned u) {
    return (u & 0x80000000u) ? __uint_as_float(u & 0x7FFFFFFFu) : __uint_as_float(~u);
}

// u64 max via shuffle butterfly (all lanes end with the max)
__device__ __forceinline__ unsigned long long shflmax64(unsigned long long k) {
#pragma unroll
    for (int o = 16; o; o >>= 1) {
        unsigned long long k2 = __shfl_xor_sync(0xFFFFFFFFu, k, o);
        k = (k2 > k) ? k2 : k;
    }
    return k;
}

// ---------------- Morton cell id + histogram (launch #1) --------------------
__global__ void cell_kernel(const float* __restrict__ pos) {
    int i = blockIdx.x * 256 + threadIdx.x;
    if (i < N_PTS) {
        float x = pos[3*i], y = pos[3*i+1], z = pos[3*i+2];
        int cx = min(GRID_C-1, max(0, (int)((x + 5.0f) * 0.8f)));
        int cy = min(GRID_C-1, max(0, (int)((y + 5.0f) * 0.8f)));
        int cz = min(GRID_C-1, max(0, (int)((z + 5.0f) * 0.8f)));
        int c = 0;
#pragma unroll
        for (int b = 0; b < 3; b++) {
            c |= ((cx >> b) & 1) << (3*b + 2);
            c |= ((cy >> b) & 1) << (3*b + 1);
            c |= ((cz >> b) & 1) << (3*b + 0);
        }
        g_cell[i] = c;
        atomicAdd(&g_cnt[c], 1);
    }
}

// ---------------- scan of 512 cell counts -> g_cur; re-zero g_cnt (#2) ------
__global__ void scan_kernel() {
    __shared__ int ws[16];
    int t = threadIdx.x;           // 512 threads, 1 cell each
    int lane = t & 31, wid = t >> 5;
    int s = g_cnt[t];
    g_cnt[t] = 0;                  // clean histogram for the NEXT graph replay
    int inc = s;
#pragma unroll
    for (int o = 1; o < 32; o <<= 1) {
        int v = __shfl_up_sync(0xFFFFFFFFu, inc, o);
        if (lane >= o) inc += v;
    }
    if (lane == 31) ws[wid] = inc;
    __syncthreads();
    if (t < 16) {
        int v = ws[t], iv = v;
#pragma unroll
        for (int o = 1; o < 16; o <<= 1) {
            int u = __shfl_up_sync(0xFFFFu, iv, o);
            if (t >= o) iv += u;
        }
        ws[t] = iv - v;            // exclusive warp base
    }
    __syncthreads();
    g_cur[t] = ws[wid] + inc - s;  // exclusive prefix
}

// ---------------- scatter coords+ids into Morton-sorted order (#3) ----------
__global__ void scatter_kernel(const float* __restrict__ pos) {
    int i = blockIdx.x * 256 + threadIdx.x;
    if (i < N_PTS) {
        int c = g_cell[i];
        int d = atomicAdd(&g_cur[c], 1);
        g_rx[d] = pos[3*i]; g_ry[d] = pos[3*i+1]; g_rz[d] = pos[3*i+2];
        g_rid16[d] = (unsigned short)i;
    }
}

// ---------------- FPS (#4 -> gets profiled by the harness ncu capture) ------
// Conflict-free phys layout: sorted point s at phys(s)=(s>>4)+(s&15)*1024 ->
// thread t's points at px[t + j*1024], lane-consecutive LDS. Payloads in
// registers; hot loop has zero global loads. Winner key = (md_bits<<32)|
// ((16383-orig)<<14 | s): max d, tie -> min original index == jnp.argmax,
// order-invariant w.r.t. the nondeterministic scatter.
// Prune: warp skips update iff all lanes prove every owned point has d>=md
// (margins >> fp32 rounding) -> fminf no-op. NEW: inactive warps also skip
// stage-1 reduce+publish: their md (hence warp-reduced key) is bit-unchanged,
// so wk[wid] from the previous iteration is still exact. wk is written only
// by its owner warp and read only after the barrier -> race-free.
__global__ __launch_bounds__(1024, 1)
void fps_kernel(const float* __restrict__ pos) {
    extern __shared__ float sm[];
    float* px = sm;
    float* py = sm + N_PTS;
    float* pz = sm + 2*N_PTS;
    __shared__ unsigned long long wk[32];
    __shared__ unsigned long long s_win;

    int t = threadIdx.x, lane = t & 31, wid = t >> 5;
    for (int i = t; i < N_PTS; i += 1024) {
        int ph = (i >> 4) + ((i & 15) << 10);
        px[ph] = g_rx[i]; py[ph] = g_ry[i]; pz[ph] = g_rz[i];
    }
    __syncthreads();

    float md[16];
    unsigned pay[16];
    float lox = FLT_MAX_C, hix = -FLT_MAX_C;
    float loy = FLT_MAX_C, hiy = -FLT_MAX_C;
    float loz = FLT_MAX_C, hiz = -FLT_MAX_C;
#pragma unroll
    for (int j = 0; j < 16; j++) {
        float x = px[t + (j << 10)], y = py[t + (j << 10)], z = pz[t + (j << 10)];
        lox = fminf(lox, x); hix = fmaxf(hix, x);
        loy = fminf(loy, y); hiy = fmaxf(hiy, y);
        loz = fminf(loz, z); hiz = fmaxf(hiz, z);
        md[j] = FLT_MAX_C;
        int s = t*16 + j;
        pay[j] = ((unsigned)(16383 - (int)g_rid16[s]) << 14) | (unsigned)s;
    }
    if (t == 0) g_idx[0] = 0;
    float lx = pos[0], ly = pos[1], lz = pos[2];   // original point 0

    unsigned long long ck = 0x7F7FFFFF00000000ull; // tmax=FLT_MAX -> first iter active

    for (int it = 1; it < M_PTS; ++it) {
        float tmax = __uint_as_float((unsigned)(ck >> 32));
        float lbx = fmaxf(fmaxf(lox - lx, lx - hix), 0.0f);
        float lby = fmaxf(fmaxf(loy - ly, ly - hiy), 0.0f);
        float lbz = fmaxf(fmaxf(loz - lz, lz - hiz), 0.0f);
        float lb2 = lbx*lbx + lby*lby + lbz*lbz;
        bool act = !(lb2 * 0.999f >= tmax * 1.0001f + 1e-8f);
        if (__ballot_sync(0xFFFFFFFFu, act)) {
            unsigned long long nk = 0;
#pragma unroll
            for (int j = 0; j < 16; j++) {
                float dx = __fsub_rn(px[t + (j << 10)], lx);
                float dy = __fsub_rn(py[t + (j << 10)], ly);
                float dz = __fsub_rn(pz[t + (j << 10)], lz);
                float d  = __fadd_rn(__fadd_rn(__fmul_rn(dx,dx), __fmul_rn(dy,dy)),
                                     __fmul_rn(dz,dz));
                float m  = fminf(md[j], d);
                md[j] = m;
                unsigned long long kj = ((unsigned long long)__float_as_uint(m) << 32)
                                      | pay[j];
                nk = (kj > nk) ? kj : nk;
            }
            ck = nk;
            // stage 1 only for warps whose keys could have changed
            unsigned long long k = shflmax64(ck);
            if (lane == 0) wk[wid] = k;
        }
        __syncthreads();
        // stage 2: warp 0 reduces the 32 warp keys
        if (t < 32) {
            unsigned long long k = shflmax64(wk[t]);
            if (t == 0) s_win = k;
        }
        __syncthreads();
        unsigned long long w = s_win;
        int sp = (int)(w & 0x3FFF);                 // winner's sorted position
        int ph = (sp >> 4) + ((sp & 15) << 10);
        lx = px[ph]; ly = py[ph]; lz = pz[ph];
        if (t == 0) g_idx[it] = 16383 - (int)((w >> 14) & 0x3FFF);
    }
}

// ---------------- ||pos||^2 (#5; only knn consumes g_sn) --------------------
__global__ void sn_kernel(const float* __restrict__ pos) {
    int i = blockIdx.x * 256 + threadIdx.x;
    if (i < N_PTS) {
        float x = pos[3*i], y = pos[3*i+1], z = pos[3*i+2];
        g_sn[i] = __fadd_rn(__fadd_rn(__fmul_rn(x,x), __fmul_rn(y,y)), __fmul_rn(z,z));
    }
}

// ---------------- gather: x_s, pos_s (+sumsq), write pos_s to output --------
__global__ void gather_kernel(const float* __restrict__ pos, const float* __restrict__ x,
                              float* __restrict__ out) {
    int gid = blockIdx.x * 256 + threadIdx.x;   // 0 .. M*64-1
    int m = gid >> 6, c = gid & 63;
    int i = g_idx[m];
    g_xs[gid] = x[i*64 + c];
    if (c == 0) {
        float a = pos[3*i], b = pos[3*i+1], d = pos[3*i+2];
        float s = __fadd_rn(__fadd_rn(__fmul_rn(a,a), __fmul_rn(b,b)), __fmul_rn(d,d));
        g_ps[m] = make_float4(a, b, d, s);
        out[262144 + m*3 + 0] = a;
        out[262144 + m*3 + 1] = b;
        out[262144 + m*3 + 2] = d;
    }
}

// ---------------- h-MLP on sampled points: delta = h(x_s)  [M,3] ------------
__global__ void h_kernel(const float* __restrict__ w1, const float* __restrict__ b1,
                         const float* __restrict__ w2, const float* __restrict__ b2) {
    __shared__ float xr[64];
    __shared__ float hid[64];
    int m = blockIdx.x, c = threadIdx.x;
    xr[c] = g_xs[m*64 + c];
    __syncthreads();
    float h = b1[c];
#pragma unroll 8
    for (int k = 0; k < 64; k++) h = fmaf(xr[k], w1[k*64 + c], h);
    hid[c] = fmaxf(h, 0.0f);
    __syncthreads();
    if (c < 3) {
        float o = b2[c];
#pragma unroll 8
        for (int k = 0; k < 64; k++) o = fmaf(hid[k], w2[k*3 + c], o);
        g_delta[m*3 + c] = o;
    }
}

// ---------------- u = x @ f_w1[3:,:] + f_b1   [N,64] (pre-ReLU) -------------
__global__ void u_kernel(const float* __restrict__ x, const float* __restrict__ fw1,
                         const float* __restrict__ fb1) {
    __shared__ float xr[64];
    int n = blockIdx.x, c = threadIdx.x;
    xr[c] = x[n*64 + c];
    __syncthreads();
    float h = fb1[c];
#pragma unroll 8
    for (int k = 0; k < 64; k++) h = fmaf(xr[k], fw1[(3 + k)*64 + c], h);
    g_u[n*64 + c] = h;
}

// ---------------- KNN: per query scan 4096, stable top-16 -------------------
__global__ void knn_kernel(const float* __restrict__ pos, float* __restrict__ out) {
    extern __shared__ float4 sp[];
    int tid = threadIdx.x;
    for (int i = tid; i < M_PTS; i += 128) sp[i] = g_ps[i];
    __syncthreads();
    int n = blockIdx.x * 128 + tid;
    float qx = pos[3*n], qy = pos[3*n+1], qz = pos[3*n+2];
    float s_n = g_sn[n];
    float bd[KNN_K]; int bi[KNN_K];
#pragma unroll
    for (int j = 0; j < KNN_K; j++) { bd[j] = FLT_MAX_C; bi[j] = 0x7FFFFFFF; }
    float worst = FLT_MAX_C;
    for (int m = 0; m < M_PTS; m++) {
        float4 q = sp[m];
        float dot = __fmaf_rn(qz, q.z, __fmaf_rn(qy, q.y, __fmul_rn(qx, q.x)));
        float d2 = __fsub_rn(__fadd_rn(s_n, q.w), __fmul_rn(2.0f, dot));
        if (d2 < worst) {                   // strict: equal d2 -> earlier index kept
            float v = d2; int id = m;
#pragma unroll
            for (int j = 0; j < KNN_K; j++) {
                if (v < bd[j]) {
                    float tv = bd[j]; bd[j] = v;  v = tv;
                    int   ti = bi[j]; bi[j] = id; id = ti;
                }
            }
            worst = bd[KNN_K-1];
        }
    }
    float* osrc = out + 274432;
    float* otgt = out + 536576;
#pragma unroll
    for (int j = 0; j < KNN_K; j++) {
        g_nbr[n*KNN_K + j] = bi[j];
        osrc[n*KNN_K + j] = (float)n;
        otgt[n*KNN_K + j] = (float)bi[j];
    }
}

// ---------------- zero the aggregation buffer -------------------------------
__global__ void zero_aggr_kernel() {
    g_aggr[blockIdx.x * 256 + threadIdx.x] = 0u;
}

// ---------------- per-edge layer-1: hidden = relu(u[src] + a @ W3) ----------
__global__ void hidden_kernel(const float* __restrict__ pos, const float* __restrict__ fw1) {
    __shared__ float w3[192];
    __shared__ float av[4][3];
    int tid = threadIdx.x;                 // 256
    if (tid < 192) w3[tid] = fw1[tid];     // rows 0..2 of f_w1
    int gid = blockIdx.x * 256 + tid;
    int e = gid >> 6, c = gid & 63;
    int eg = tid >> 6;
    int n = e >> 4;
    int m = g_nbr[e];
    if (c < 3) {
        float pcomp = pos[3*n + c];
        float qcomp = ((const float*)&g_ps[m])[c];
        av[eg][c] = __fadd_rn(__fsub_rn(pcomp, qcomp), g_delta[m*3 + c]);
    }
    __syncthreads();
    float h = g_u[n*64 + c];
    h = fmaf(av[eg][0], w3[c],       h);
    h = fmaf(av[eg][1], w3[64 + c],  h);
    h = fmaf(av[eg][2], w3[128 + c], h);
    g_hidden[gid] = fmaxf(h, 0.0f);
}

// ---------------- per-edge layer-2 GEMM + atomicMax aggregation -------------
__global__ __launch_bounds__(128)
void msg_kernel(const float* __restrict__ fw2, const float* __restrict__ fb2) {
    __shared__ float w2s[64*64];
    __shared__ float ht[32*65];           // padded to kill bank conflicts
    __shared__ int   tg[32];
    int tid = threadIdx.x;
    for (int i = tid; i < 4096; i += 128) w2s[i] = fw2[i];
    int e0 = blockIdx.x * 32;
    for (int i = tid; i < 2048; i += 128) {
        ht[(i >> 6)*65 + (i & 63)] = g_hidden[e0*64 + i];
    }
    if (tid < 32) tg[tid] = g_nbr[e0 + tid];
    __syncthreads();

    int te = (tid >> 4) * 4;              // edge base within tile
    int td = (tid & 15) * 4;              // output-dim base
    float acc[4][4];
    float b0 = fb2[td], b1 = fb2[td+1], b2v = fb2[td+2], b3 = fb2[td+3];
#pragma unroll
    for (int i = 0; i < 4; i++) { acc[i][0]=b0; acc[i][1]=b1; acc[i][2]=b2v; acc[i][3]=b3; }

#pragma unroll 4
    for (int k = 0; k < 64; k++) {
        float4 w = *(const float4*)&w2s[k*64 + td];
#pragma unroll
        for (int i = 0; i < 4; i++) {
            float hv = ht[(te + i)*65 + k];
            acc[i][0] = fmaf(hv, w.x, acc[i][0]);
            acc[i][1] = fmaf(hv, w.y, acc[i][1]);
            acc[i][2] = fmaf(hv, w.z, acc[i][2]);
            acc[i][3] = fmaf(hv, w.w, acc[i][3]);
        }
    }
#pragma unroll
    for (int i = 0; i < 4; i++) {
        unsigned* base = &g_aggr[tg[te + i]*64 + td];
        atomicMax(base + 0, encf(acc[i][0]));
        atomicMax(base + 1, encf(acc[i][1]));
        atomicMax(base + 2, encf(acc[i][2]));
        atomicMax(base + 3, encf(acc[i][3]));
    }
}

// ---------------- g-MLP + residual -> x_new (written as f32) ----------------
__global__ void out_kernel(const float* __restrict__ w1, const float* __restrict__ b1,
                           const float* __restrict__ w2, const float* __restrict__ b2,
                           float* __restrict__ out) {
    __shared__ float in[128];
    __shared__ float hid[64];
    int m = blockIdx.x, c = threadIdx.x;
    float xs = g_xs[m*64 + c];
    in[c] = xs;
    unsigned u = g_aggr[m*64 + c];
    in[64 + c] = (u == 0u) ? 0.0f : decf(u);   // isfinite-else-0 rule
    __syncthreads();
    float h = b1[c];
#pragma unroll 8
    for (int k = 0; k < 128; k++) h = fmaf(in[k], w1[k*64 + c], h);
    hid[c] = fmaxf(h, 0.0f);
    __syncthreads();
    float o = b2[c];
#pragma unroll 8
    for (int k = 0; k < 64; k++) o = fmaf(hid[k], w2[k*64 + c], o);
    out[m*64 + c] = xs + o;
}

// ---------------- launcher --------------------------------------------------
extern "C" void kernel_launch(void* const* d_in, const int* in_sizes, int n_in,
                              void* d_out, int out_size) {
    const float* x    = (const float*)d_in[0];
    const float* pos  = (const float*)d_in[1];
    // d_in[2] = edge_index (int64) -- unused by the reference math
    const float* h_w1 = (const float*)d_in[3];
    const float* h_b1 = (const float*)d_in[4];
    const float* h_w2 = (const float*)d_in[5];
    const float* h_b2 = (const float*)d_in[6];
    const float* f_w1 = (const float*)d_in[7];
    const float* f_b1 = (const float*)d_in[8];
    const float* f_w2 = (const float*)d_in[9];
    const float* f_b2 = (const float*)d_in[10];
    const float* g_w1 = (const float*)d_in[11];
    const float* g_b1 = (const float*)d_in[12];
    const float* g_w2 = (const float*)d_in[13];
    const float* g_b2 = (const float*)d_in[14];
    float* out = (float*)d_out;

    size_t fps_smem = (size_t)(3*N_PTS)*sizeof(float);          // 192 KB
    cudaFuncSetAttribute(fps_kernel, cudaFuncAttributeMaxDynamicSharedMemorySize, (int)fps_smem);
    cudaFuncSetAttribute(knn_kernel, cudaFuncAttributeMaxDynamicSharedMemorySize, M_PTS*16);

    // fps_kernel is deliberately the 4th launch: the harness ncu capture has
    // been landing on launch #4 every round, so this round it profiles FPS.
    cell_kernel<<<(N_PTS + 255)/256, 256>>>(pos);       // g_cnt zeroed at load / by scan
    scan_kernel<<<1, NCELL>>>();                        // also re-zeroes g_cnt
    scatter_kernel<<<(N_PTS + 255)/256, 256>>>(pos);
    fps_kernel<<<1, 1024, fps_smem>>>(pos);
    sn_kernel<<<(N_PTS + 255)/256, 256>>>(pos);
    gather_kernel<<<(M_PTS*EMB)/256, 256>>>(pos, x, out);
    h_kernel<<<M_PTS, 64>>>(h_w1, h_b1, h_w2, h_b2);
    u_kernel<<<N_PTS, 64>>>(x, f_w1, f_b1);
    zero_aggr_kernel<<<(M_PTS*EMB)/256, 256>>>();
    knn_kernel<<<N_PTS/128, 128, M_PTS*16>>>(pos, out);
    hidden_kernel<<<(NEDGE*EMB)/256, 256>>>(pos, f_w1);
    msg_kernel<<<NEDGE/32, 128>>>(f_w2, f_b2);
    out_kernel<<<M_PTS, 64>>>(g_w1, g_b1, g_w2, g_b2, out);
}